// round 9
// baseline (speedup 1.0000x reference)
#include <cuda_runtime.h>
#include <cuda_fp16.h>

// Problem constants
#define NN      100000
#define EE      1600000
#define CC      25000          // N / PF
#define KDIM    136            // 128 svec + 3 ea + 3 r + 2 pad

// Emit bucketing: 8 src-clusters per block
#define NBKT    8
#define BWRD    782            // ceil(25000/32) words per bucket bitmap
#define TOTW    (NBKT * BWRD)  // 6256
#define WPT     25             // words per thread (256 thr): 256*25=6400 >= 6256
#define NB_EMIT (CC / NBKT)    // 3125

// Output layout (float32, flattened tuple in return order)
#define XN_OFF  0
#define NP_OFF  3200000
#define EI0_OFF 3275000
#define EI1_OFF 4875000
#define EAT_OFF 6475000
#define NB_OFF  11275000

// ---------------- static device scratch ----------------
__device__ __align__(16) int   g_cnt[CC];               // dst-cluster histogram
__device__ __align__(16) int   g_cnt2[CC];              // src-cluster histogram
__device__ __align__(16) int   g_off[CC + 4];
__device__ __align__(16) int   g_off2[CC + 4];
__device__ __align__(16) int   g_cur[CC];
__device__ __align__(16) int   g_cur2[CC];
__device__ __align__(16) int4  g_scat[EE];              // (src, ea0, ea1, ea2) dst-cluster-sorted
__device__ __align__(16) int   g_scat2[EE];             // dst-cluster id, src-cluster-sorted
__device__ __align__(16) __half g_xh[NN * 128];         // fp16 copy of x
__device__ __align__(16) float g_svec[CC * KDIM];       // per-cluster GEMM input rows
__device__ __align__(16) float g_Wext[KDIM * 128];      // [Wconv_feat@Wg ; Wedge_feat@Wg ; Wgattr ; 0]
__device__ unsigned long long g_state[NB_EMIT];         // decoupled-lookback state
__device__ int g_total;

// ---------------- kernels ----------------

// Zero counters/state + convert x to fp16
__global__ void k_zero(const float* __restrict__ x) {
    int tid = blockIdx.x * blockDim.x + threadIdx.x;
    int stride = gridDim.x * blockDim.x;
    for (int i = tid; i < CC; i += stride) { g_cnt[i] = 0; g_cnt2[i] = 0; }
    for (int i = tid; i < NB_EMIT; i += stride) g_state[i] = 0ull;
    const float4* x4 = (const float4*)x;
    uint2* xh2 = (uint2*)g_xh;
    for (int i = tid; i < NN * 32; i += stride) {
        float4 v = x4[i];
        __half2 a = __floats2half2_rn(v.x, v.y);
        __half2 b = __floats2half2_rn(v.z, v.w);
        xh2[i] = make_uint2(*(unsigned*)&a, *(unsigned*)&b);
    }
}

// Weight folding + per-cluster small outputs (new_pos, residual->svec, new_batch)
__global__ void k_prep(const float* __restrict__ Wconv, const float* __restrict__ Wedge,
                       const float* __restrict__ Wg, const float* __restrict__ Wgattr,
                       const float* __restrict__ pos, const int* __restrict__ batch,
                       float* __restrict__ dout) {
    int b = blockIdx.x;
    int j = threadIdx.x;                    // 0..127
    if (b < 128) {                          // Wconv[:,16:] @ Wg  -> rows 0..127
        float acc = 0.0f;
        #pragma unroll 8
        for (int t = 0; t < 128; t++) acc += Wconv[b * 144 + 16 + t] * Wg[t * 128 + j];
        g_Wext[b * 128 + j] = acc;
    } else if (b < 131) {                   // Wedge[:,16:] @ Wg  -> rows 128..130
        int a = b - 128;
        float acc = 0.0f;
        #pragma unroll 8
        for (int t = 0; t < 128; t++) acc += Wedge[a * 144 + 16 + t] * Wg[t * 128 + j];
        g_Wext[b * 128 + j] = acc;
    } else if (b < 134) {                   // Wgattr -> rows 131..133
        g_Wext[b * 128 + j] = Wgattr[(b - 131) * 128 + j];
    } else if (b < 136) {                   // pad rows 134..135
        g_Wext[b * 128 + j] = 0.0f;
    } else {                                // cluster blocks
        int c = (b - 136) * 128 + j;
        if (c >= CC) return;
        int base = c * 4;
        float px[4], py[4], pz[4];
        float sx = 0.f, sy = 0.f, sz = 0.f;
        #pragma unroll
        for (int i = 0; i < 4; i++) {
            px[i] = pos[(base + i) * 3 + 0];
            py[i] = pos[(base + i) * 3 + 1];
            pz[i] = pos[(base + i) * 3 + 2];
            sx += px[i]; sy += py[i]; sz += pz[i];
        }
        float nx = sx * 0.25f, ny = sy * 0.25f, nz = sz * 0.25f;
        dout[NP_OFF + c * 3 + 0] = nx;
        dout[NP_OFF + c * 3 + 1] = ny;
        dout[NP_OFF + c * 3 + 2] = nz;
        float rx = 0.f, ry = 0.f, rz = 0.f;
        #pragma unroll
        for (int i = 0; i < 4; i++) { rx += px[i] - nx; ry += py[i] - ny; rz += pz[i] - nz; }
        g_svec[c * KDIM + 131] = rx;
        g_svec[c * KDIM + 132] = ry;
        g_svec[c * KDIM + 133] = rz;
        int bm = batch[base];
        #pragma unroll
        for (int i = 1; i < 4; i++) { int v = batch[base + i]; bm = (v > bm) ? v : bm; }
        dout[NB_OFF + c] = (float)bm;
    }
}

// Edge pass 1: dual histogram (dst-cluster and src-cluster)
__global__ void k_edge1(const int* __restrict__ ei) {
    int e = blockIdx.x * blockDim.x + threadIdx.x;
    if (e >= EE) return;
    int a = ei[e] >> 2;
    int c = ei[EE + e] >> 2;
    atomicAdd(&g_cnt[c], 1);
    atomicAdd(&g_cnt2[a], 1);
}

// Single-pass scan: 2 blocks, each scans one 25000-array; thread owns 25 elems
__global__ void k_scan2() {
    __shared__ int wsum[32];
    const int which = blockIdx.x;
    const int* in = which ? g_cnt2 : g_cnt;
    int* out = which ? g_off2 : g_off;
    int* cur = which ? g_cur2 : g_cur;
    const int tid = threadIdx.x, lane = tid & 31, wid = tid >> 5;
    const int base = tid * 25;
    int v[25];
    int sum = 0;
    #pragma unroll
    for (int i = 0; i < 25; i++) {
        int idx = base + i;
        int t = (idx < CC) ? in[idx] : 0;
        v[i] = t; sum += t;
    }
    int incl = sum;
    #pragma unroll
    for (int d = 1; d < 32; d <<= 1) {
        int y = __shfl_up_sync(0xffffffffu, incl, d);
        if (lane >= d) incl += y;
    }
    if (lane == 31) wsum[wid] = incl;
    __syncthreads();
    if (wid == 0) {
        int w = wsum[lane];
        int wi = w;
        #pragma unroll
        for (int d = 1; d < 32; d <<= 1) {
            int y = __shfl_up_sync(0xffffffffu, wi, d);
            if (lane >= d) wi += y;
        }
        wsum[lane] = wi - w;
    }
    __syncthreads();
    int run = wsum[wid] + (incl - sum);
    #pragma unroll
    for (int i = 0; i < 25; i++) {
        int idx = base + i;
        if (idx < CC) { out[idx] = run; cur[idx] = run; }
        run += v[i];
    }
    if (tid == 0) out[CC] = EE;
}

// Dual scatter: (src, ea) by dst-cluster; dst-cluster id by src-cluster
__global__ void k_scatter(const int* __restrict__ ei, const float* __restrict__ ea) {
    int e = blockIdx.x * blockDim.x + threadIdx.x;
    if (e >= EE) return;
    int s = ei[e];
    int d = ei[EE + e];
    int c = d >> 2;
    int a = s >> 2;
    float a0 = ea[e * 3 + 0], a1 = ea[e * 3 + 1], a2 = ea[e * 3 + 2];
    int p = atomicAdd(&g_cur[c], 1);
    g_scat[p] = make_int4(s, __float_as_int(a0), __float_as_int(a1), __float_as_int(a2));
    int p2 = atomicAdd(&g_cur2[a], 1);
    g_scat2[p2] = c;
}

// One block per cluster: fp16 gather-sum of x rows + ea sum -> g_svec row
__global__ void __launch_bounds__(128) k_pool() {
    __shared__ int   sidx[128];
    __shared__ float sacc[4][128];
    __shared__ float sea[3][4];
    const int c = blockIdx.x;
    const int tid = threadIdx.x;
    const int g = tid >> 5, l = tid & 31;
    const int start = g_off[c], end = g_off[c + 1];
    const uint2* xp2 = (const uint2*)g_xh;   // row stride 32 uint2 (128 halfs)
    float fx0 = 0.f, fx1 = 0.f, fx2 = 0.f, fx3 = 0.f;
    float ex = 0.f, ey = 0.f, ez = 0.f;
    for (int p = start; p < end; p += 128) {
        int nl = min(128, end - p);
        __syncthreads();
        if (tid < nl) {
            int4 q = g_scat[p + tid];
            sidx[tid] = q.x;
            ex += __int_as_float(q.y);
            ey += __int_as_float(q.z);
            ez += __int_as_float(q.w);
        }
        __syncthreads();
        int r = 0;
        for (; r + 8 <= nl; r += 8) {
            int ra = sidx[r + g], rb = sidx[r + g + 4];
            uint2 ua = xp2[ra * 32 + l];
            uint2 ub = xp2[rb * 32 + l];
            __half2 h0 = *(__half2*)&ua.x, h1 = *(__half2*)&ua.y;
            __half2 h2 = *(__half2*)&ub.x, h3 = *(__half2*)&ub.y;
            float2 f0 = __half22float2(h0), f1 = __half22float2(h1);
            float2 f2 = __half22float2(h2), f3 = __half22float2(h3);
            fx0 += f0.x + f2.x; fx1 += f0.y + f2.y;
            fx2 += f1.x + f3.x; fx3 += f1.y + f3.y;
        }
        for (; r + 4 <= nl; r += 4) {
            int ra = sidx[r + g];
            uint2 ua = xp2[ra * 32 + l];
            __half2 h0 = *(__half2*)&ua.x, h1 = *(__half2*)&ua.y;
            float2 f0 = __half22float2(h0), f1 = __half22float2(h1);
            fx0 += f0.x; fx1 += f0.y; fx2 += f1.x; fx3 += f1.y;
        }
        int rem = nl - r;
        if (g < rem) {
            int ra = sidx[r + g];
            uint2 ua = xp2[ra * 32 + l];
            __half2 h0 = *(__half2*)&ua.x, h1 = *(__half2*)&ua.y;
            float2 f0 = __half22float2(h0), f1 = __half22float2(h1);
            fx0 += f0.x; fx1 += f0.y; fx2 += f1.x; fx3 += f1.y;
        }
    }
    sacc[g][4 * l + 0] = fx0;
    sacc[g][4 * l + 1] = fx1;
    sacc[g][4 * l + 2] = fx2;
    sacc[g][4 * l + 3] = fx3;
    #pragma unroll
    for (int d = 16; d; d >>= 1) {
        ex += __shfl_down_sync(0xffffffffu, ex, d);
        ey += __shfl_down_sync(0xffffffffu, ey, d);
        ez += __shfl_down_sync(0xffffffffu, ez, d);
    }
    if (l == 0) { sea[0][g] = ex; sea[1][g] = ey; sea[2][g] = ez; }
    __syncthreads();
    g_svec[c * KDIM + tid] = sacc[0][tid] + sacc[1][tid] + sacc[2][tid] + sacc[3][tid];
    if (tid < 3) g_svec[c * KDIM + 128 + tid] = sea[tid][0] + sea[tid][1] + sea[tid][2] + sea[tid][3];
    if (tid < 2) g_svec[c * KDIM + 134 + tid] = 0.0f;
}

// Register-tiled GEMM: x_new[25000][128] = 0.25 * svec[25000][136] @ Wext[136][128]
__global__ void __launch_bounds__(256) k_gemm(float* __restrict__ dout) {
    __shared__ float sS[8][128];
    __shared__ float sW[8][128];
    const int tid = threadIdx.x;
    const int ty = tid >> 4, tx = tid & 15;
    const int row0 = blockIdx.x * 128;
    float acc[8][8];
    #pragma unroll
    for (int i = 0; i < 8; i++)
        #pragma unroll
        for (int j = 0; j < 8; j++) acc[i][j] = 0.0f;

    const int rl = tid >> 1, kq = (tid & 1) * 4;
    const int kk = tid >> 5, c4 = (tid & 31) * 4;
    for (int k0 = 0; k0 < KDIM; k0 += 8) {
        int row = row0 + rl;
        float4 v = make_float4(0.f, 0.f, 0.f, 0.f);
        if (row < CC) v = *(const float4*)(g_svec + row * KDIM + k0 + kq);
        float4 wv = *(const float4*)(g_Wext + (k0 + kk) * 128 + c4);
        __syncthreads();
        sS[kq + 0][rl] = v.x; sS[kq + 1][rl] = v.y; sS[kq + 2][rl] = v.z; sS[kq + 3][rl] = v.w;
        *(float4*)&sW[kk][c4] = wv;
        __syncthreads();
        #pragma unroll
        for (int q = 0; q < 8; q++) {
            float a[8], b[8];
            *(float4*)&a[0] = *(float4*)&sS[q][ty * 8];
            *(float4*)&a[4] = *(float4*)&sS[q][ty * 8 + 4];
            *(float4*)&b[0] = *(float4*)&sW[q][tx * 8];
            *(float4*)&b[4] = *(float4*)&sW[q][tx * 8 + 4];
            #pragma unroll
            for (int i = 0; i < 8; i++)
                #pragma unroll
                for (int j = 0; j < 8; j++) acc[i][j] += a[i] * b[j];
        }
    }
    #pragma unroll
    for (int i = 0; i < 8; i++) {
        int row = row0 + ty * 8 + i;
        if (row < CC) {
            float4 o0 = make_float4(acc[i][0] * 0.25f, acc[i][1] * 0.25f, acc[i][2] * 0.25f, acc[i][3] * 0.25f);
            float4 o1 = make_float4(acc[i][4] * 0.25f, acc[i][5] * 0.25f, acc[i][6] * 0.25f, acc[i][7] * 0.25f);
            *(float4*)(dout + XN_OFF + row * 128 + tx * 8) = o0;
            *(float4*)(dout + XN_OFF + row * 128 + tx * 8 + 4) = o1;
        }
    }
}

// Emit: block handles 8 src-cluster buckets with smem bitmaps; ordered unique emit
// via decoupled lookback. Output order = ascending (a, d2) = ascending enc = sorted unique.
__global__ void __launch_bounds__(256) k_emit(float* __restrict__ dout) {
    __shared__ unsigned sbm[NBKT][BWRD];     // 25,024 B
    __shared__ float snp[NBKT][3];
    __shared__ int warp_sums[8];
    __shared__ int s_prefix;
    const int tid = threadIdx.x, b = blockIdx.x;
    const int lane = tid & 31, wid = tid >> 5;
    const int a0 = b * NBKT;
    unsigned* flat = (unsigned*)sbm;
    for (int i = tid; i < TOTW; i += 256) flat[i] = 0u;
    if (tid < NBKT * 3) ((float*)snp)[tid] = dout[NP_OFF + a0 * 3 + tid];
    __syncthreads();
    #pragma unroll
    for (int k = 0; k < NBKT; k++) {
        int s = g_off2[a0 + k], e = g_off2[a0 + k + 1];
        for (int p = s + tid; p < e; p += 256) {
            int d = g_scat2[p];
            atomicOr(&sbm[k][d >> 5], 1u << (d & 31));
        }
    }
    __syncthreads();
    // per-thread popcount over its contiguous word range
    const int w0 = tid * WPT;
    int cnt = 0;
    #pragma unroll
    for (int i = 0; i < WPT; i++) {
        int w = w0 + i;
        if (w < TOTW) cnt += __popc(flat[w]);
    }
    int incl = cnt;
    #pragma unroll
    for (int d = 1; d < 32; d <<= 1) {
        int y = __shfl_up_sync(0xffffffffu, incl, d);
        if (lane >= d) incl += y;
    }
    if (lane == 31) warp_sums[wid] = incl;
    __syncthreads();
    if (tid == 0) {
        int run = 0;
        #pragma unroll
        for (int k = 0; k < 8; k++) { int t = warp_sums[k]; warp_sums[k] = run; run += t; }
        int block_total = run;
        if (b == 0) {
            s_prefix = 0;
            atomicExch(&g_state[0], (2ull << 32) | (unsigned)block_total);
        } else {
            atomicExch(&g_state[b], (1ull << 32) | (unsigned)block_total);
            int run2 = 0;
            int j = b - 1;
            while (1) {
                unsigned long long s;
                do { s = atomicAdd(&g_state[j], 0ull); } while ((s >> 32) == 0ull);
                run2 += (int)(unsigned)s;
                if ((s >> 32) == 2ull) break;
                j--;
            }
            s_prefix = run2;
            atomicExch(&g_state[b], (2ull << 32) | (unsigned)(run2 + block_total));
            if (b == NB_EMIT - 1) g_total = run2 + block_total;
        }
    }
    __syncthreads();
    int pos = s_prefix + warp_sums[wid] + (incl - cnt);
    float* e0 = dout + EI0_OFF;
    float* e1 = dout + EI1_OFF;
    float* eat = dout + EAT_OFF;
    const float* np = dout + NP_OFF;
    #pragma unroll 1
    for (int i = 0; i < WPT; i++) {
        int w = w0 + i;
        if (w >= TOTW) break;
        unsigned ww = flat[w];
        if (!ww) continue;
        int k = w / BWRD;
        int wi = w - k * BWRD;
        int a = a0 + k;
        int dbase = wi << 5;
        float nax = snp[k][0], nay = snp[k][1], naz = snp[k][2];
        while (ww) {
            int bit = __ffs(ww) - 1;
            ww &= ww - 1;
            int d2 = dbase + bit;
            e0[pos] = (float)a;
            e1[pos] = (float)d2;
            eat[pos * 3 + 0] = np[d2 * 3 + 0] - nax;
            eat[pos * 3 + 1] = np[d2 * 3 + 1] - nay;
            eat[pos * 3 + 2] = np[d2 * 3 + 2] - naz;
            pos++;
        }
    }
}

// Zero the fill tail [g_total, E) of the edge outputs
__global__ void k_tail(float* __restrict__ dout) {
    int i = blockIdx.x * blockDim.x + threadIdx.x;
    int total = g_total;
    if (i >= total && i < EE) {
        dout[EI0_OFF + i] = 0.0f;
        dout[EI1_OFF + i] = 0.0f;
        dout[EAT_OFF + 3 * i + 0] = 0.0f;
        dout[EAT_OFF + 3 * i + 1] = 0.0f;
        dout[EAT_OFF + 3 * i + 2] = 0.0f;
    }
}

// ---------------- launch ----------------
extern "C" void kernel_launch(void* const* d_in, const int* in_sizes, int n_in,
                              void* d_out, int out_size) {
    const float* x      = (const float*)d_in[0];
    const float* pos    = (const float*)d_in[1];
    const int*   ei     = (const int*)  d_in[2];
    const float* ea     = (const float*)d_in[3];
    const int*   batch  = (const int*)  d_in[4];
    const float* Wconv  = (const float*)d_in[5];
    const float* Wedge  = (const float*)d_in[6];
    // d_in[7] = D_bloom : dead in the reference
    const float* Wg     = (const float*)d_in[8];
    const float* Wgattr = (const float*)d_in[9];
    float* out = (float*)d_out;

    k_zero<<<2048, 256>>>(x);
    k_prep<<<136 + (CC + 127) / 128, 128>>>(Wconv, Wedge, Wg, Wgattr, pos, batch, out);
    k_edge1<<<(EE + 255) / 256, 256>>>(ei);
    k_scan2<<<2, 1024>>>();
    k_scatter<<<(EE + 255) / 256, 256>>>(ei, ea);
    k_pool<<<CC, 128>>>();
    k_gemm<<<(CC + 127) / 128, 256>>>(out);
    k_emit<<<NB_EMIT, 256>>>(out);
    k_tail<<<(EE + 255) / 256, 256>>>(out);
}